// round 2
// baseline (speedup 1.0000x reference)
#include <cuda_runtime.h>

#define BATCH 64
#define IN    1024
#define OUT   1024
#define DM    64
#define HID   256

// scratch (no cudaMalloc allowed)
__device__ float g_Px[32*HID];      // pe_x @ W1[0:64]   + b1
__device__ float g_Py[32*HID];      // pe_y @ W1[64:128]
__device__ float g_Pb[32*HID];      // pe_b @ Wb1[32:96] + bb1
__device__ float g_s [BATCH];       // sum_g x[b,g]
__device__ float g_Q [BATCH*32*HID];// (Px + xchunk@W1[128:160]) * 2*log2(e)
__device__ float g_Hp[BATCH*4*HID]; // partial H

#define TWO_LOG2E 2.8853900817779268f
#define LOG2_10000 13.287712379549449f

__device__ __forceinline__ float ex2a(float x){ float r; asm("ex2.approx.f32 %0, %1;" : "=f"(r) : "f"(x)); return r; }
__device__ __forceinline__ float rcpa(float x){ float r; asm("rcp.approx.f32 %0, %1;" : "=f"(r) : "f"(x)); return r; }
// tanh(z) given t = z * 2*log2(e):  1 - 2/(exp(2z)+1)
__device__ __forceinline__ float tanh_t(float t){ return fmaf(-2.0f, rcpa(ex2a(t) + 1.0f), 1.0f); }

// ---------------------------------------------------------------- K1
// bid<32: Px(+b1), <64: Py, <96: Pb(+bb1), else per-b sum of x
__global__ void k1_precompute(const float* __restrict__ x,
                              const float* __restrict__ W1, const float* __restrict__ b1,
                              const float* __restrict__ Wb1, const float* __restrict__ bb1)
{
    int bid = blockIdx.x;
    int c = threadIdx.x;
    if (bid < 96) {
        int type = bid >> 5;
        int pos  = bid & 31;
        __shared__ float pe[DM];
        if (c < 32) {
            float inv = ex2a(-LOG2_10000 * ((float)c * (1.0f/32.0f)));
            float ang = (float)pos * inv;
            pe[2*c]   = sinf(ang);
            pe[2*c+1] = cosf(ang);
        }
        __syncthreads();
        const float* W;
        float acc;
        if (type == 0)      { W = W1;            acc = b1[c];  }
        else if (type == 1) { W = W1 + 64*HID;   acc = 0.0f;   }
        else                { W = Wb1 + 32*HID;  acc = bb1[c]; }
        #pragma unroll 8
        for (int d = 0; d < DM; ++d) acc = fmaf(pe[d], W[d*HID + c], acc);
        if (type == 0)      g_Px[pos*HID + c] = acc;
        else if (type == 1) g_Py[pos*HID + c] = acc;
        else                g_Pb[pos*HID + c] = acc;
    } else {
        int b = bid - 96;
        __shared__ float red[256];
        float s = 0.0f;
        for (int i = c; i < IN; i += 256) s += x[b*IN + i];
        red[c] = s; __syncthreads();
        for (int off = 128; off > 0; off >>= 1) {
            if (c < off) red[c] += red[c + off];
            __syncthreads();
        }
        if (c == 0) g_s[b] = red[0];
    }
}

// ---------------------------------------------------------------- K2
// Q[b][j][c] = (Px[j][c] + sum_k x[b, j*32+k] * W1[128+k][c]) * 2log2e
__global__ void k2_Q(const float* __restrict__ x, const float* __restrict__ W1)
{
    int bj = blockIdx.x;            // b*32 + j
    int b = bj >> 5, j = bj & 31;
    int c = threadIdx.x;
    __shared__ float xs[32];
    if (c < 32) xs[c] = x[b*IN + j*32 + c];
    __syncthreads();
    float acc = g_Px[j*HID + c];
    const float* Wc = W1 + 128*HID + c;
    #pragma unroll
    for (int k = 0; k < 32; ++k) acc = fmaf(xs[k], Wc[k*HID], acc);
    g_Q[bj*HID + c] = acc * TWO_LOG2E;
}

// ---------------------------------------------------------------- K3
// Hp[b][sp][c] = sum over 8 t's, 32 j's of x[b, t*32+j]*tanh(Q[b][j]+Py[t])
__global__ void k3_main(const float* __restrict__ x)
{
    int bx = blockIdx.x;            // b*4 + sp
    int b = bx >> 2, sp = bx & 3;
    int c = threadIdx.x;
    __shared__ float xs[256];
    xs[c] = x[b*IN + sp*256 + c];
    float qv[32];
    #pragma unroll
    for (int j = 0; j < 32; ++j) qv[j] = g_Q[(b*32 + j)*HID + c];
    __syncthreads();
    float acc0 = 0.0f, acc1 = 0.0f;
    #pragma unroll 1
    for (int tt = 0; tt < 8; ++tt) {
        int t = sp*8 + tt;
        float py = g_Py[t*HID + c] * TWO_LOG2E;
        #pragma unroll
        for (int j = 0; j < 32; j += 2) {
            acc0 = fmaf(xs[tt*32 + j    ], tanh_t(qv[j    ] + py), acc0);
            acc1 = fmaf(xs[tt*32 + j + 1], tanh_t(qv[j + 1] + py), acc1);
        }
    }
    g_Hp[bx*HID + c] = acc0 + acc1;
}

// ---------------------------------------------------------------- K4 (fused out-GEMM + bias hypernetwork)
// CTA = (bg: 8 b's) x (ot: 32-col o-tile).  grid = 8*32 = 256, 256 threads.
// Phase A: out0 = H @ W2 + s*b2   (W2 streamed from gmem, H broadcast from smem)
// Phase B: hb[u][c] = tanh(Pb + oc_u @ Wb1[0:32])
// Phase C: bias = hb @ Wb2 + bb2; out = out0 + bias
__global__ void k4_fused(const float* __restrict__ W2, const float* __restrict__ b2,
                         const float* __restrict__ Wb1, const float* __restrict__ Wb2,
                         const float* __restrict__ bb2, float* __restrict__ out)
{
    int ot = blockIdx.x & 31;       // o-tile index (== bias-net position tx)
    int bg = blockIdx.x >> 5;       // b group of 8
    int t = threadIdx.x;
    __shared__ float Hs[8*HID];     // 8 KB
    __shared__ float o0s[8*32];     // 1 KB
    __shared__ float hb[8*HID];     // 8 KB

    // reduce Hp partials -> Hs[bl][c]
    for (int i = t; i < 8*HID; i += 256) {
        int bl = i >> 8, c = i & 255;
        const float* hp = g_Hp + ((bg*8 + bl)*4)*HID + c;
        Hs[i] = (hp[0] + hp[HID]) + (hp[2*HID] + hp[3*HID]);
    }
    __syncthreads();

    int ol = t & 31, bl = t >> 5;   // warp == bl (warp-uniform Hs row -> LDS broadcast)
    int o = ot*32 + ol;
    int b = bg*8 + bl;

    const float* w2p = W2 + o;
    const float* hsp = Hs + bl*HID;
    float acc = 0.0f;
    #pragma unroll 8
    for (int c = 0; c < HID; ++c)
        acc = fmaf(hsp[c], w2p[c*OUT], acc);
    float o0 = acc + g_s[b] * b2[o];
    o0s[bl*32 + ol] = o0;
    __syncthreads();

    // Phase B: thread <-> hidden channel c; loop over the 8 units (b's)
    {
        int c = t;
        float wb1r[32];
        #pragma unroll
        for (int k = 0; k < 32; ++k) wb1r[k] = Wb1[k*HID + c];
        float pb = g_Pb[ot*HID + c];
        #pragma unroll
        for (int u = 0; u < 8; ++u) {
            float a = pb;
            #pragma unroll
            for (int k = 0; k < 32; ++k) a = fmaf(o0s[u*32 + k], wb1r[k], a);
            hb[u*HID + c] = tanh_t(a * TWO_LOG2E);
        }
    }
    __syncthreads();

    // Phase C: bias + final write
    {
        float bias = bb2[ol];
        const float* hu = hb + bl*HID;      // warp-uniform -> broadcast
        #pragma unroll 8
        for (int c = 0; c < HID; ++c)
            bias = fmaf(hu[c], Wb2[c*32 + ol], bias);
        out[b*OUT + o] = o0s[bl*32 + ol] + bias;
    }
}

extern "C" void kernel_launch(void* const* d_in, const int* in_sizes, int n_in,
                              void* d_out, int out_size)
{
    const float* x   = (const float*)d_in[0];
    // d_in[1] = output_size (fixed 1024, unused)
    const float* W1  = (const float*)d_in[2];
    const float* b1  = (const float*)d_in[3];
    const float* W2  = (const float*)d_in[4];
    const float* b2  = (const float*)d_in[5];
    const float* Wb1 = (const float*)d_in[6];
    const float* bb1 = (const float*)d_in[7];
    const float* Wb2 = (const float*)d_in[8];
    const float* bb2 = (const float*)d_in[9];
    float* out = (float*)d_out;

    k1_precompute<<<160, 256>>>(x, W1, b1, Wb1, bb1);
    k2_Q<<<2048, 256>>>(x, W1);
    k3_main<<<256, 256>>>(x);
    k4_fused<<<256, 256>>>(W2, b2, Wb1, Wb2, bb2, out);
}

// round 5
// speedup vs baseline: 1.1013x; 1.1013x over previous
#include <cuda_runtime.h>

#define BATCH 64
#define IN    1024
#define OUT   1024
#define DM    64
#define HID   256

// scratch (no cudaMalloc allowed)
__device__ float g_Px[32*HID];        // pe_x @ W1[0:64]   + b1
__device__ float g_Py[32*HID];        // pe_y @ W1[64:128]
__device__ float g_Pb[32*HID];        // pe_b @ Wb1[32:96] + bb1
__device__ float g_s [BATCH];         // sum_g x[b,g]
__device__ float g_Q [BATCH*32*HID];  // (Px + xchunk@W1[128:160]) * 2*log2(e)
__device__ float g_Hp[BATCH*4*HID];   // partial H
__device__ float g_o0h[4*BATCH*OUT];  // split-K partials of H@W2 (1 MB)

#define TWO_LOG2E 2.8853900817779268f
#define LOG2_10000 13.287712379549449f

__device__ __forceinline__ float ex2a(float x){ float r; asm("ex2.approx.f32 %0, %1;" : "=f"(r) : "f"(x)); return r; }
__device__ __forceinline__ float rcpa(float x){ float r; asm("rcp.approx.f32 %0, %1;" : "=f"(r) : "f"(x)); return r; }
// tanh(z) given t = z * 2*log2(e):  1 - 2/(exp(2z)+1)
__device__ __forceinline__ float tanh_t(float t){ return fmaf(-2.0f, rcpa(ex2a(t) + 1.0f), 1.0f); }

// ---------------------------------------------------------------- K1
// bid<32: Px(+b1), <64: Py, <96: Pb(+bb1), else per-b sum of x
__global__ void k1_precompute(const float* __restrict__ x,
                              const float* __restrict__ W1, const float* __restrict__ b1,
                              const float* __restrict__ Wb1, const float* __restrict__ bb1)
{
    int bid = blockIdx.x;
    int c = threadIdx.x;
    if (bid < 96) {
        int type = bid >> 5;
        int pos  = bid & 31;
        __shared__ float pe[DM];
        if (c < 32) {
            float inv = ex2a(-LOG2_10000 * ((float)c * (1.0f/32.0f)));
            float ang = (float)pos * inv;
            pe[2*c]   = sinf(ang);
            pe[2*c+1] = cosf(ang);
        }
        __syncthreads();
        const float* W;
        float acc;
        if (type == 0)      { W = W1;            acc = b1[c];  }
        else if (type == 1) { W = W1 + 64*HID;   acc = 0.0f;   }
        else                { W = Wb1 + 32*HID;  acc = bb1[c]; }
        #pragma unroll 8
        for (int d = 0; d < DM; ++d) acc = fmaf(pe[d], W[d*HID + c], acc);
        if (type == 0)      g_Px[pos*HID + c] = acc;
        else if (type == 1) g_Py[pos*HID + c] = acc;
        else                g_Pb[pos*HID + c] = acc;
    } else {
        int b = bid - 96;
        __shared__ float red[256];
        float s = 0.0f;
        for (int i = c; i < IN; i += 256) s += x[b*IN + i];
        red[c] = s; __syncthreads();
        for (int off = 128; off > 0; off >>= 1) {
            if (c < off) red[c] += red[c + off];
            __syncthreads();
        }
        if (c == 0) g_s[b] = red[0];
    }
}

// ---------------------------------------------------------------- K2
// Q[b][j][c] = (Px[j][c] + sum_k x[b, j*32+k] * W1[128+k][c]) * 2log2e
__global__ void k2_Q(const float* __restrict__ x, const float* __restrict__ W1)
{
    int bj = blockIdx.x;            // b*32 + j
    int b = bj >> 5, j = bj & 31;
    int c = threadIdx.x;
    __shared__ float xs[32];
    if (c < 32) xs[c] = x[b*IN + j*32 + c];
    __syncthreads();
    float acc = g_Px[j*HID + c];
    const float* Wc = W1 + 128*HID + c;
    #pragma unroll
    for (int k = 0; k < 32; ++k) acc = fmaf(xs[k], Wc[k*HID], acc);
    g_Q[bj*HID + c] = acc * TWO_LOG2E;
}

// ---------------------------------------------------------------- K3
// Hp[b][sp][c] = sum over 8 t's, 32 j's of x[b, t*32+j]*tanh(Q[b][j]+Py[t])
__global__ void k3_main(const float* __restrict__ x)
{
    int bx = blockIdx.x;            // b*4 + sp
    int b = bx >> 2, sp = bx & 3;
    int c = threadIdx.x;
    __shared__ float xs[256];
    xs[c] = x[b*IN + sp*256 + c];
    float qv[32];
    #pragma unroll
    for (int j = 0; j < 32; ++j) qv[j] = g_Q[(b*32 + j)*HID + c];
    __syncthreads();
    float acc0 = 0.0f, acc1 = 0.0f;
    #pragma unroll 1
    for (int tt = 0; tt < 8; ++tt) {
        int t = sp*8 + tt;
        float py = g_Py[t*HID + c] * TWO_LOG2E;
        #pragma unroll
        for (int j = 0; j < 32; j += 2) {
            acc0 = fmaf(xs[tt*32 + j    ], tanh_t(qv[j    ] + py), acc0);
            acc1 = fmaf(xs[tt*32 + j + 1], tanh_t(qv[j + 1] + py), acc1);
        }
    }
    g_Hp[bx*HID + c] = acc0 + acc1;
}

// ---------------------------------------------------------------- K4a
// Split-K GEMM partials: g_o0h[ch][b][o] = H[b][ch*64:+64] @ W2[ch*64:+64][o]
// grid 512 = (bg:8 of 8b) x (ot:16 of 64o) x (ch:4 of 64c), 256 threads.
__global__ __launch_bounds__(256) void k4a_gemm(const float* __restrict__ W2)
{
    int bid = blockIdx.x;
    int ch = bid & 3;
    int ot = (bid >> 2) & 15;
    int bg = bid >> 6;
    int t = threadIdx.x;
    __shared__ float2 W2s[64*32];   // [cc][o-pair]  16 KB
    __shared__ float  Hs[8*64];     // 2 KB

    const float* W2base = W2 + (ch*64)*OUT + ot*64;
    #pragma unroll
    for (int i = t; i < 64*32; i += 256) {
        int cc = i >> 5, op = i & 31;
        W2s[i] = *(const float2*)(W2base + cc*OUT + op*2);
    }
    #pragma unroll
    for (int i = t; i < 8*64; i += 256) {
        int bl = i >> 6, cc = i & 63;
        const float* hp = g_Hp + ((bg*8 + bl)*4)*HID + ch*64 + cc;
        Hs[i] = (hp[0] + hp[HID]) + (hp[2*HID] + hp[3*HID]);
    }
    __syncthreads();

    int bl = t >> 5, op = t & 31;
    const float* hs = Hs + bl*64;
    float ax = 0.0f, ay = 0.0f;
    #pragma unroll 8
    for (int cc = 0; cc < 64; ++cc) {
        float h = hs[cc];               // warp-uniform -> LDS broadcast
        float2 w = W2s[cc*32 + op];
        ax = fmaf(h, w.x, ax);
        ay = fmaf(h, w.y, ay);
    }
    int b = bg*8 + bl;
    int o = ot*64 + op*2;
    float2 r; r.x = ax; r.y = ay;
    *(float2*)&g_o0h[(ch*BATCH + b)*OUT + o] = r;
}

// ---------------------------------------------------------------- K4b
// Reduce partials + s*b2, then bias hypernetwork, final add.
// grid 512 = (b:64) x (q:8 groups of 4 tx positions), 256 threads.
__global__ __launch_bounds__(256) void k4b_bias(const float* __restrict__ b2,
                                                const float* __restrict__ Wb1,
                                                const float* __restrict__ Wb2,
                                                const float* __restrict__ bb2,
                                                float* __restrict__ out)
{
    int bid = blockIdx.x;
    int b = bid >> 3, q = bid & 7;
    int t = threadIdx.x;
    __shared__ float ocs[128];          // out0 for this b, o in [q*128, q*128+128)
    __shared__ float Wb1s[32*HID];      // 32 KB
    __shared__ float hbs[4*HID];        // 4 KB

    float sb = g_s[b];
    if (t < 128) {
        int o = q*128 + t;
        const float* p = g_o0h + b*OUT + o;
        float v = (p[0] + p[BATCH*OUT]) + (p[2*BATCH*OUT] + p[3*BATCH*OUT]);
        ocs[t] = v + sb * b2[o];
    }
    #pragma unroll
    for (int i = t; i < 32*HID; i += 256) Wb1s[i] = Wb1[i];   // rows 0..31 contiguous
    __syncthreads();

    // hb for 4 tx units; thread <-> hidden channel c
    {
        int c = t;
        #pragma unroll
        for (int u = 0; u < 4; ++u) {
            int tx = q*4 + u;
            float a = g_Pb[tx*HID + c];
            #pragma unroll
            for (int k = 0; k < 32; ++k)
                a = fmaf(ocs[u*32 + k], Wb1s[k*HID + c], a);   // ocs broadcast
            hbs[u*HID + c] = tanh_t(a * TWO_LOG2E);
        }
    }
    __syncthreads();

    if (t < 128) {
        int u = t >> 5, ol = t & 31;
        float bias = bb2[ol];
        const float* hu = hbs + u*HID;  // warp-uniform -> broadcast
        #pragma unroll 8
        for (int c = 0; c < HID; ++c)
            bias = fmaf(hu[c], Wb2[c*32 + ol], bias);
        out[b*OUT + q*128 + u*32 + ol] = ocs[u*32 + ol] + bias;
    }
}

extern "C" void kernel_launch(void* const* d_in, const int* in_sizes, int n_in,
                              void* d_out, int out_size)
{
    const float* x   = (const float*)d_in[0];
    // d_in[1] = output_size (fixed 1024, unused)
    const float* W1  = (const float*)d_in[2];
    const float* b1  = (const float*)d_in[3];
    const float* W2  = (const float*)d_in[4];
    const float* b2  = (const float*)d_in[5];
    const float* Wb1 = (const float*)d_in[6];
    const float* bb1 = (const float*)d_in[7];
    const float* Wb2 = (const float*)d_in[8];
    const float* bb2 = (const float*)d_in[9];
    float* out = (float*)d_out;

    k1_precompute<<<160, 256>>>(x, W1, b1, Wb1, bb1);
    k2_Q<<<2048, 256>>>(x, W1);
    k3_main<<<256, 256>>>(x);
    k4a_gemm<<<512, 256>>>(W2);
    k4b_bias<<<512, 256>>>(b2, Wb1, Wb2, bb2, out);
}

// round 8
// speedup vs baseline: 1.1574x; 1.0510x over previous
#include <cuda_runtime.h>

#define BATCH 64
#define IN    1024
#define OUT   1024
#define DM    64
#define HID   256
#define CH    8                      // split-K chunks (32 c's each)

// scratch (no cudaMalloc allowed)
__device__ float g_Px[32*HID];        // pe_x @ W1[0:64]   + b1
__device__ float g_Py[32*HID];        // pe_y @ W1[64:128]
__device__ float g_Pb[32*HID];        // pe_b @ Wb1[32:96] + bb1
__device__ float g_s [BATCH];         // sum_g x[b,g]
__device__ float g_Hp[BATCH*4*HID];   // partial H
__device__ float g_o0h[CH*BATCH*OUT]; // split-K partials of H@W2 (2 MB)

#define TWO_LOG2E 2.8853900817779268f
#define LOG2_10000 13.287712379549449f

__device__ __forceinline__ float ex2a(float x){ float r; asm("ex2.approx.f32 %0, %1;" : "=f"(r) : "f"(x)); return r; }
__device__ __forceinline__ float rcpa(float x){ float r; asm("rcp.approx.f32 %0, %1;" : "=f"(r) : "f"(x)); return r; }
// tanh(z) given t = z * 2*log2(e):  1 - 2/(exp(2z)+1)
__device__ __forceinline__ float tanh_t(float t){ return fmaf(-2.0f, rcpa(ex2a(t) + 1.0f), 1.0f); }

// ---------------------------------------------------------------- K1
// bid<32: Px(+b1), <64: Py, <96: Pb(+bb1), else per-b sum of x
__global__ void k1_precompute(const float* __restrict__ x,
                              const float* __restrict__ W1, const float* __restrict__ b1,
                              const float* __restrict__ Wb1, const float* __restrict__ bb1)
{
    int bid = blockIdx.x;
    int c = threadIdx.x;
    if (bid < 96) {
        int type = bid >> 5;
        int pos  = bid & 31;
        __shared__ float pe[DM];
        if (c < 32) {
            float inv = ex2a(-LOG2_10000 * ((float)c * (1.0f/32.0f)));
            float ang = (float)pos * inv;
            pe[2*c]   = sinf(ang);
            pe[2*c+1] = cosf(ang);
        }
        __syncthreads();
        const float* W;
        float acc;
        if (type == 0)      { W = W1;            acc = b1[c];  }
        else if (type == 1) { W = W1 + 64*HID;   acc = 0.0f;   }
        else                { W = Wb1 + 32*HID;  acc = bb1[c]; }
        #pragma unroll 8
        for (int d = 0; d < DM; ++d) acc = fmaf(pe[d], W[d*HID + c], acc);
        if (type == 0)      g_Px[pos*HID + c] = acc;
        else if (type == 1) g_Py[pos*HID + c] = acc;
        else                g_Pb[pos*HID + c] = acc;
    } else {
        int b = bid - 96;
        __shared__ float red[256];
        float s = 0.0f;
        for (int i = c; i < IN; i += 256) s += x[b*IN + i];
        red[c] = s; __syncthreads();
        for (int off = 128; off > 0; off >>= 1) {
            if (c < off) red[c] += red[c + off];
            __syncthreads();
        }
        if (c == 0) g_s[b] = red[0];
    }
}

// ---------------------------------------------------------------- K3 (fused Q + tanh-contraction)
// CTA = (b, sp).  Per thread (channel c):
//   qv[j] = (Px[j][c] + sum_k x[b,j*32+k]*W1[128+k][c]) * 2log2e      (Q recompute)
//   Hp[b][sp][c] = sum_{tt,j} x[b, (sp*8+tt)*32+j] * tanh(qv[j] + Py[sp*8+tt][c])
__global__ __launch_bounds__(256) void k3_main(const float* __restrict__ x,
                                               const float* __restrict__ W1)
{
    int bx = blockIdx.x;            // b*4 + sp
    int b = bx >> 2, sp = bx & 3;
    int c = threadIdx.x;
    __shared__ float xs[IN];        // whole row of x (4 KB)

    #pragma unroll
    for (int i = 0; i < 4; ++i) xs[i*256 + c] = x[b*IN + i*256 + c];

    // W1[128+k][c] column in registers (coalesced loads)
    float w1r[32];
    const float* Wc = W1 + 128*HID + c;
    #pragma unroll
    for (int k = 0; k < 32; ++k) w1r[k] = Wc[k*HID];
    __syncthreads();

    // Q phase
    float qv[32];
    #pragma unroll
    for (int j = 0; j < 32; ++j) {
        float a = g_Px[j*HID + c];
        const float4* x4 = (const float4*)(xs + j*32);
        #pragma unroll
        for (int k4 = 0; k4 < 8; ++k4) {
            float4 v = x4[k4];
            a = fmaf(v.x, w1r[4*k4 + 0], a);
            a = fmaf(v.y, w1r[4*k4 + 1], a);
            a = fmaf(v.z, w1r[4*k4 + 2], a);
            a = fmaf(v.w, w1r[4*k4 + 3], a);
        }
        qv[j] = a * TWO_LOG2E;
    }

    // tanh contraction over this sp's 8 t-chunks
    float acc0 = 0.0f, acc1 = 0.0f;
    #pragma unroll 1
    for (int tt = 0; tt < 8; ++tt) {
        int t = sp*8 + tt;
        float py = g_Py[t*HID + c] * TWO_LOG2E;
        const float* xv = xs + sp*256 + tt*32;
        #pragma unroll
        for (int j = 0; j < 32; j += 2) {
            acc0 = fmaf(xv[j    ], tanh_t(qv[j    ] + py), acc0);
            acc1 = fmaf(xv[j + 1], tanh_t(qv[j + 1] + py), acc1);
        }
    }
    g_Hp[bx*HID + c] = acc0 + acc1;
}

// ---------------------------------------------------------------- K4a
// Split-K GEMM partials: g_o0h[ch][b][o] = H[b][ch*32:+32] @ W2[ch*32:+32][o]
// grid 1024 = (bg:8 of 8b) x (ot:16 of 64o) x (ch:8 of 32c), 256 threads.
__global__ __launch_bounds__(256) void k4a_gemm(const float* __restrict__ W2)
{
    int bid = blockIdx.x;
    int ch = bid & 7;
    int ot = (bid >> 3) & 15;
    int bg = bid >> 7;
    int t = threadIdx.x;
    __shared__ float2 W2s[32*32];   // [cc][o-pair]  8 KB
    __shared__ float  Hs[8*32];     // 1 KB

    const float* W2base = W2 + (ch*32)*OUT + ot*64;
    #pragma unroll
    for (int i = t; i < 32*32; i += 256) {
        int cc = i >> 5, op = i & 31;
        W2s[i] = *(const float2*)(W2base + cc*OUT + op*2);
    }
    {
        int bl = t >> 5, cc = t & 31;
        const float* hp = g_Hp + ((bg*8 + bl)*4)*HID + ch*32 + cc;
        Hs[t] = (hp[0] + hp[HID]) + (hp[2*HID] + hp[3*HID]);
    }
    __syncthreads();

    int bl = t >> 5, op = t & 31;
    const float* hs = Hs + bl*32;
    float ax = 0.0f, ay = 0.0f;
    #pragma unroll
    for (int cc = 0; cc < 32; ++cc) {
        float h = hs[cc];               // warp-uniform -> LDS broadcast
        float2 w = W2s[cc*32 + op];
        ax = fmaf(h, w.x, ax);
        ay = fmaf(h, w.y, ay);
    }
    int b = bg*8 + bl;
    int o = ot*64 + op*2;
    float2 r; r.x = ax; r.y = ay;
    *(float2*)&g_o0h[(ch*BATCH + b)*OUT + o] = r;
}

// ---------------------------------------------------------------- K4b
// Reduce partials + s*b2, then bias hypernetwork, final add.
// grid 512 = (b:64) x (q:8 groups of 4 tx positions), 256 threads.
__global__ __launch_bounds__(256) void k4b_bias(const float* __restrict__ b2,
                                                const float* __restrict__ Wb1,
                                                const float* __restrict__ Wb2,
                                                const float* __restrict__ bb2,
                                                float* __restrict__ out)
{
    int bid = blockIdx.x;
    int b = bid >> 3, q = bid & 7;
    int t = threadIdx.x;
    __shared__ float ocs[128];          // out0 for this b, o in [q*128, q*128+128)
    __shared__ float hbs[4*HID];        // 4 KB

    if (t < 128) {
        int o = q*128 + t;
        const float* p = g_o0h + b*OUT + o;
        float v = 0.0f;
        #pragma unroll
        for (int ch = 0; ch < CH; ++ch) v += p[ch*BATCH*OUT];
        ocs[t] = v + g_s[b] * b2[o];
    }

    // Wb1 rows 0..31, column c -> registers (coalesced; L1-shared across CTAs)
    float wb1r[32];
    {
        const float* Wc = Wb1 + t;
        #pragma unroll
        for (int k = 0; k < 32; ++k) wb1r[k] = Wc[k*HID];
    }
    __syncthreads();

    // hb for 4 tx units; thread <-> hidden channel c
    {
        int c = t;
        #pragma unroll
        for (int u = 0; u < 4; ++u) {
            int tx = q*4 + u;
            float a = g_Pb[tx*HID + c];
            #pragma unroll
            for (int k = 0; k < 32; ++k)
                a = fmaf(ocs[u*32 + k], wb1r[k], a);   // ocs broadcast
            hbs[u*HID + c] = tanh_t(a * TWO_LOG2E);
        }
    }
    __syncthreads();

    if (t < 128) {
        int u = t >> 5, ol = t & 31;
        float bias = bb2[ol];
        const float* hu = hbs + u*HID;  // warp-uniform -> broadcast
        #pragma unroll 8
        for (int c = 0; c < HID; ++c)
            bias = fmaf(hu[c], Wb2[c*32 + ol], bias);
        out[b*OUT + q*128 + u*32 + ol] = ocs[u*32 + ol] + bias;
    }
}

extern "C" void kernel_launch(void* const* d_in, const int* in_sizes, int n_in,
                              void* d_out, int out_size)
{
    const float* x   = (const float*)d_in[0];
    // d_in[1] = output_size (fixed 1024, unused)
    const float* W1  = (const float*)d_in[2];
    const float* b1  = (const float*)d_in[3];
    const float* W2  = (const float*)d_in[4];
    const float* b2  = (const float*)d_in[5];
    const float* Wb1 = (const float*)d_in[6];
    const float* bb1 = (const float*)d_in[7];
    const float* Wb2 = (const float*)d_in[8];
    const float* bb2 = (const float*)d_in[9];
    float* out = (float*)d_out;

    k1_precompute<<<160, 256>>>(x, W1, b1, Wb1, bb1);
    k3_main<<<256, 256>>>(x, W1);
    k4a_gemm<<<1024, 256>>>(W2);
    k4b_bias<<<512, 256>>>(b2, Wb1, Wb2, bb2, out);
}

// round 9
// speedup vs baseline: 1.4204x; 1.2272x over previous
#include <cuda_runtime.h>

#define BATCH 64
#define IN    1024
#define OUT   1024
#define DM    64
#define HID   256
#define CH    8                      // split-K chunks (32 c's each)

// scratch (no cudaMalloc allowed)
__device__ float g_Px[32*HID];        // pe_x @ W1[0:64]   + b1
__device__ float g_Py[32*HID];        // pe_y @ W1[64:128]
__device__ float g_Pb[32*HID];        // pe_b @ Wb1[32:96] + bb1
__device__ float g_s [BATCH];         // sum_g x[b,g]
__device__ float g_Hp[BATCH*4*HID];   // partial H
__device__ float g_o0h[CH*BATCH*OUT]; // split-K partials of H@W2 (2 MB)

#define LOG2_10000 13.287712379549449f

__device__ __forceinline__ float ex2a(float x){ float r; asm("ex2.approx.f32 %0, %1;" : "=f"(r) : "f"(x)); return r; }
__device__ __forceinline__ float tanha(float x){ float r; asm("tanh.approx.f32 %0, %1;" : "=f"(r) : "f"(x)); return r; }

// ---------------------------------------------------------------- K1
// bid<32: Px(+b1), <64: Py, <96: Pb(+bb1), else per-b sum of x
__global__ void k1_precompute(const float* __restrict__ x,
                              const float* __restrict__ W1, const float* __restrict__ b1,
                              const float* __restrict__ Wb1, const float* __restrict__ bb1)
{
    int bid = blockIdx.x;
    int c = threadIdx.x;
    if (bid < 96) {
        int type = bid >> 5;
        int pos  = bid & 31;
        __shared__ float pe[DM];
        if (c < 32) {
            float inv = ex2a(-LOG2_10000 * ((float)c * (1.0f/32.0f)));
            float ang = (float)pos * inv;
            pe[2*c]   = sinf(ang);
            pe[2*c+1] = cosf(ang);
        }
        __syncthreads();
        const float* W;
        float acc;
        if (type == 0)      { W = W1;            acc = b1[c];  }
        else if (type == 1) { W = W1 + 64*HID;   acc = 0.0f;   }
        else                { W = Wb1 + 32*HID;  acc = bb1[c]; }
        #pragma unroll 8
        for (int d = 0; d < DM; ++d) acc = fmaf(pe[d], W[d*HID + c], acc);
        if (type == 0)      g_Px[pos*HID + c] = acc;
        else if (type == 1) g_Py[pos*HID + c] = acc;
        else                g_Pb[pos*HID + c] = acc;
    } else {
        int b = bid - 96;
        __shared__ float red[256];
        float s = 0.0f;
        for (int i = c; i < IN; i += 256) s += x[b*IN + i];
        red[c] = s; __syncthreads();
        for (int off = 128; off > 0; off >>= 1) {
            if (c < off) red[c] += red[c + off];
            __syncthreads();
        }
        if (c == 0) g_s[b] = red[0];
    }
}

// ---------------------------------------------------------------- K3 (fused Q + tanh-contraction)
// CTA = (b, sp).  Per thread (channel c):
//   qv[j] = Px[j][c] + sum_k x[b,j*32+k]*W1[128+k][c]
//   Hp[b][sp][c] = sum_{tt,j} x[b,(sp*8+tt)*32+j] * tanh(qv[j] + Py[sp*8+tt][c])
__global__ __launch_bounds__(256) void k3_main(const float* __restrict__ x,
                                               const float* __restrict__ W1)
{
    int bx = blockIdx.x;            // b*4 + sp
    int b = bx >> 2, sp = bx & 3;
    int c = threadIdx.x;
    __shared__ float xs[IN];        // whole row of x (4 KB)

    #pragma unroll
    for (int i = 0; i < 4; ++i) xs[i*256 + c] = x[b*IN + i*256 + c];

    // W1[128+k][c] column in registers (coalesced loads)
    float w1r[32];
    const float* Wc = W1 + 128*HID + c;
    #pragma unroll
    for (int k = 0; k < 32; ++k) w1r[k] = Wc[k*HID];
    __syncthreads();

    // Q phase
    float qv[32];
    #pragma unroll
    for (int j = 0; j < 32; ++j) {
        float a = g_Px[j*HID + c];
        const float4* x4 = (const float4*)(xs + j*32);
        #pragma unroll
        for (int k4 = 0; k4 < 8; ++k4) {
            float4 v = x4[k4];
            a = fmaf(v.x, w1r[4*k4 + 0], a);
            a = fmaf(v.y, w1r[4*k4 + 1], a);
            a = fmaf(v.z, w1r[4*k4 + 2], a);
            a = fmaf(v.w, w1r[4*k4 + 3], a);
        }
        qv[j] = a;
    }

    // tanh contraction over this sp's 8 t-chunks
    float acc0 = 0.0f, acc1 = 0.0f;
    #pragma unroll 1
    for (int tt = 0; tt < 8; ++tt) {
        int t = sp*8 + tt;
        float py = g_Py[t*HID + c];
        const float* xv = xs + sp*256 + tt*32;
        #pragma unroll
        for (int j = 0; j < 32; j += 2) {
            acc0 = fmaf(xv[j    ], tanha(qv[j    ] + py), acc0);
            acc1 = fmaf(xv[j + 1], tanha(qv[j + 1] + py), acc1);
        }
    }
    g_Hp[bx*HID + c] = acc0 + acc1;
}

// ---------------------------------------------------------------- K4a
// Split-K GEMM partials: g_o0h[ch][b][o] = H[b][ch*32:+32] @ W2[ch*32:+32][o]
// grid 1024 = (bg:8 of 8b) x (ot:16 of 64o) x (ch:8 of 32c), 256 threads.
__global__ __launch_bounds__(256) void k4a_gemm(const float* __restrict__ W2)
{
    int bid = blockIdx.x;
    int ch = bid & 7;
    int ot = (bid >> 3) & 15;
    int bg = bid >> 7;
    int t = threadIdx.x;
    __shared__ float2 W2s[32*32];   // [cc][o-pair]  8 KB
    __shared__ float  Hs[8*32];     // 1 KB

    const float* W2base = W2 + (ch*32)*OUT + ot*64;
    #pragma unroll
    for (int i = t; i < 32*32; i += 256) {
        int cc = i >> 5, op = i & 31;
        W2s[i] = *(const float2*)(W2base + cc*OUT + op*2);
    }
    {
        int bl = t >> 5, cc = t & 31;
        const float* hp = g_Hp + ((bg*8 + bl)*4)*HID + ch*32 + cc;
        Hs[t] = (hp[0] + hp[HID]) + (hp[2*HID] + hp[3*HID]);
    }
    __syncthreads();

    int bl = t >> 5, op = t & 31;
    const float* hs = Hs + bl*32;
    float ax = 0.0f, ay = 0.0f;
    #pragma unroll
    for (int cc = 0; cc < 32; ++cc) {
        float h = hs[cc];               // warp-uniform -> LDS broadcast
        float2 w = W2s[cc*32 + op];
        ax = fmaf(h, w.x, ax);
        ay = fmaf(h, w.y, ay);
    }
    int b = bg*8 + bl;
    int o = ot*64 + op*2;
    float2 r; r.x = ax; r.y = ay;
    *(float2*)&g_o0h[(ch*BATCH + b)*OUT + o] = r;
}

// ---------------------------------------------------------------- K4b
// Reduce partials + s*b2, then bias hypernetwork, final add.
// grid 512 = (b:64) x (q:8 groups of 4 tx positions), 256 threads.
// All phases use all 256 threads; dependency chains split via 2 c-halves
// and multi-accumulator unrolling.
__global__ __launch_bounds__(256) void k4b_bias(const float* __restrict__ b2,
                                                const float* __restrict__ Wb1,
                                                const float* __restrict__ Wb2,
                                                const float* __restrict__ bb2,
                                                float* __restrict__ out)
{
    int bid = blockIdx.x;
    int b = bid >> 3, q = bid & 7;
    int t = threadIdx.x;
    __shared__ float ocs[128];          // out0 for this b, o in [q*128, +128)
    __shared__ float hbs[4*HID];        // 4 KB
    __shared__ float pc[256];           // cross-half partials

    // Phase A: reduce split-K partials. 256 threads = 2 ch-halves x 128 o's.
    {
        int half = t >> 7, o_l = t & 127;
        const float* p = g_o0h + ((half*4)*BATCH + b)*OUT + q*128 + o_l;
        float v0 = p[0], v1 = p[BATCH*OUT], v2 = p[2*BATCH*OUT], v3 = p[3*BATCH*OUT];
        pc[t] = (v0 + v1) + (v2 + v3);
    }

    // Wb1 rows 0..31, column t -> registers (coalesced; independent of smem)
    float wb1r[32];
    {
        const float* Wc = Wb1 + t;
        #pragma unroll
        for (int k = 0; k < 32; ++k) wb1r[k] = Wc[k*HID];
    }
    __syncthreads();
    if (t < 128) {
        int o = q*128 + t;
        ocs[t] = pc[t] + pc[t + 128] + g_s[b] * b2[o];
    }
    __syncthreads();

    // Phase B: thread <-> hidden channel c; 4 units as 4 parallel accumulators
    {
        int c = t;
        float a0 = g_Pb[(q*4 + 0)*HID + c];
        float a1 = g_Pb[(q*4 + 1)*HID + c];
        float a2 = g_Pb[(q*4 + 2)*HID + c];
        float a3 = g_Pb[(q*4 + 3)*HID + c];
        #pragma unroll
        for (int k = 0; k < 32; ++k) {
            float w = wb1r[k];
            a0 = fmaf(ocs[k      ], w, a0);
            a1 = fmaf(ocs[32  + k], w, a1);
            a2 = fmaf(ocs[64  + k], w, a2);
            a3 = fmaf(ocs[96  + k], w, a3);
        }
        hbs[0*HID + c] = tanha(a0);
        hbs[1*HID + c] = tanha(a1);
        hbs[2*HID + c] = tanha(a2);
        hbs[3*HID + c] = tanha(a3);
    }
    __syncthreads();

    // Phase C: 256 threads = 2 c-halves x (4 units x 32 o-lanes); 4 accumulators
    {
        int half = t >> 7, idx = t & 127;
        int u = idx >> 5, ol = idx & 31;
        const float* hu = hbs + u*HID + half*128;   // warp-uniform -> broadcast
        const float* w  = Wb2 + half*128*32 + ol;   // coalesced per warp
        float a0 = 0.f, a1 = 0.f, a2 = 0.f, a3 = 0.f;
        #pragma unroll
        for (int cc = 0; cc < 128; cc += 4) {
            a0 = fmaf(hu[cc    ], w[(cc    )*32], a0);
            a1 = fmaf(hu[cc + 1], w[(cc + 1)*32], a1);
            a2 = fmaf(hu[cc + 2], w[(cc + 2)*32], a2);
            a3 = fmaf(hu[cc + 3], w[(cc + 3)*32], a3);
        }
        pc[t] = (a0 + a1) + (a2 + a3);
    }
    __syncthreads();

    if (t < 128) {
        int u = t >> 5, ol = t & 31;
        out[b*OUT + q*128 + t] = ocs[t] + pc[t] + pc[t + 128] + bb2[ol];
    }
}

extern "C" void kernel_launch(void* const* d_in, const int* in_sizes, int n_in,
                              void* d_out, int out_size)
{
    const float* x   = (const float*)d_in[0];
    // d_in[1] = output_size (fixed 1024, unused)
    const float* W1  = (const float*)d_in[2];
    const float* b1  = (const float*)d_in[3];
    const float* W2  = (const float*)d_in[4];
    const float* b2  = (const float*)d_in[5];
    const float* Wb1 = (const float*)d_in[6];
    const float* bb1 = (const float*)d_in[7];
    const float* Wb2 = (const float*)d_in[8];
    const float* bb2 = (const float*)d_in[9];
    float* out = (float*)d_out;

    k1_precompute<<<160, 256>>>(x, W1, b1, Wb1, bb1);
    k3_main<<<256, 256>>>(x, W1);
    k4a_gemm<<<1024, 256>>>(W2);
    k4b_bias<<<512, 256>>>(b2, Wb1, Wb2, bb2, out);
}